// round 3
// baseline (speedup 1.0000x reference)
#include <cuda_runtime.h>
#include <math.h>

#define BATCH 4096
#define T_STEPS 48
#define FEAT 35
#define HID 1024
#define GN (4*HID)
#define INP_PAD 80   // padded [x_c(35), m(35), 0...] width

// ---------------- device scratch (no allocation allowed) ----------------
__device__ float g_gamma[(size_t)BATCH * T_STEPS * HID];  // precomputed decay
__device__ float g_hdec[BATCH * HID];                      // h after decay (GEMM A)
__device__ float g_h[BATCH * HID];
__device__ float g_c[BATCH * HID];
__device__ float g_inp[BATCH * INP_PAD];                   // [x_c, m] padded
__device__ float g_bias[GN];                               // b_ih + b_hh
__device__ float g_xnum[T_STEPS];                          // per-step |x-xh|*m sums
__device__ float g_mden[T_STEPS];                          // per-step sum(m)
__device__ float g_ynum;
__device__ float g_yden;

__device__ __forceinline__ float warp_sum(float v) {
    #pragma unroll
    for (int o = 16; o > 0; o >>= 1) v += __shfl_down_sync(0xffffffffu, v, o);
    return v;
}
__device__ __forceinline__ float sigmoidf_(float x) { return 1.f / (1.f + expf(-x)); }

// ---------------- init: zero state + combine biases ----------------
__global__ void init_kernel(const float* __restrict__ b_ih, const float* __restrict__ b_hh) {
    long idx = (long)blockIdx.x * blockDim.x + threadIdx.x;
    long stride = (long)gridDim.x * blockDim.x;
    const long NH = (long)BATCH * HID;
    for (long i = idx; i < NH; i += stride) { g_h[i] = 0.f; g_c[i] = 0.f; }
    for (long i = idx; i < (long)BATCH * INP_PAD; i += stride) g_inp[i] = 0.f;
    for (long i = idx; i < GN; i += stride) g_bias[i] = b_ih[i] + b_hh[i];
    if (idx < T_STEPS) g_xnum[idx] = 0.f;
    if (idx == 0) { g_ynum = 0.f; g_yden = 0.f; }
}

// ---------------- precompute gamma = exp(-relu(deltas @ td_W^T + td_b)) ----------------
// rows = B*T (196608), cols = HID. grid (6144, 4), block 256.
__global__ void __launch_bounds__(256) gamma_kernel(const float* __restrict__ deltas,
                                                    const float* __restrict__ td_W,
                                                    const float* __restrict__ td_b) {
    const int r0 = blockIdx.x * 32;
    const int j0 = blockIdx.y * 256;
    __shared__ float sd[32][36];
    __shared__ float sw[256 * FEAT];
    for (int i = threadIdx.x; i < 32 * FEAT; i += 256) {
        int r = i / FEAT, k = i - r * FEAT;
        sd[r][k] = deltas[(long)(r0 + r) * FEAT + k];
    }
    for (int i = threadIdx.x; i < 256 * FEAT; i += 256)
        sw[i] = td_W[(long)j0 * FEAT + i];   // cols contiguous -> contiguous chunk
    __syncthreads();
    const int c = threadIdx.x;
    float wreg[FEAT];
    #pragma unroll
    for (int k = 0; k < FEAT; k++) wreg[k] = sw[c * FEAT + k];
    const float bias = td_b[j0 + c];
    for (int r = 0; r < 32; r++) {
        float a = bias;
        #pragma unroll
        for (int k = 0; k < FEAT; k++) a += sd[r][k] * wreg[k];
        float rel = fmaxf(a, 0.f);
        g_gamma[(long)(r0 + r) * HID + j0 + c] = expf(-rel);
    }
}

// ---------------- precompute per-step sum of masks ----------------
__global__ void summask_kernel(const float* __restrict__ masks) {
    const int t = blockIdx.x;
    float s = 0.f;
    for (int i = threadIdx.x; i < BATCH * FEAT; i += 256) {
        int b = i / FEAT, f = i - b * FEAT;
        s += masks[((long)b * T_STEPS + t) * FEAT + f];
    }
    __shared__ float red[256];
    red[threadIdx.x] = s; __syncthreads();
    for (int o = 128; o > 0; o >>= 1) {
        if (threadIdx.x < o) red[threadIdx.x] += red[threadIdx.x + o];
        __syncthreads();
    }
    if (threadIdx.x == 0) g_mden[t] = red[0];
}

// ---------------- per-step S1: decay + regression + imputation + x_loss ----------------
// 8 batch rows per block, 256 threads (8 warps, warp w owns row w).
__global__ void __launch_bounds__(256) step1_kernel(int t,
        const float* __restrict__ values, const float* __restrict__ masks,
        const float* __restrict__ reg_W, const float* __restrict__ reg_b,
        float* __restrict__ d_imp) {
    const int b0 = blockIdx.x * 8;
    const int tid = threadIdx.x;
    __shared__ float shd[8][HID];
    __shared__ float warp_loss[8];
    for (int i = tid; i < 8 * HID; i += 256) {
        int r = i >> 10, k = i & (HID - 1);
        int b = b0 + r;
        float hv = g_h[(long)b * HID + k] * g_gamma[((long)b * T_STEPS + t) * HID + k];
        shd[r][k] = hv;
        g_hdec[(long)b * HID + k] = hv;
    }
    __syncthreads();
    const int warp = tid >> 5, lane = tid & 31;
    const int b = b0 + warp;
    float lloss = 0.f;
    for (int f = 0; f < FEAT; f++) {
        float s = 0.f;
        for (int k = lane; k < HID; k += 32) s += shd[warp][k] * reg_W[(long)f * HID + k];
        s = warp_sum(s);
        if (lane == 0) {
            float xh = s + reg_b[f];
            long off = ((long)b * T_STEPS + t) * FEAT + f;
            float x = values[off], m = masks[off];
            float xc = m * x + (1.f - m) * xh;
            d_imp[off] = xc;
            g_inp[b * INP_PAD + f] = xc;
            g_inp[b * INP_PAD + FEAT + f] = m;
            lloss += fabsf(x - xh) * m;
        }
    }
    if (lane == 0) warp_loss[warp] = lloss;
    __syncthreads();
    if (tid == 0) {
        float s = 0.f;
        #pragma unroll
        for (int w = 0; w < 8; w++) s += warp_loss[w];
        atomicAdd(&g_xnum[t], s);
    }
}

// ---------------- per-step S2: fused gates GEMM + LSTM pointwise ----------------
// tile: 128 batch x 16 j (x 4 gates = 64 local cols), K = 1024 (h) + 80 (padded inputs)
__global__ void __launch_bounds__(256) step2_kernel(const float* __restrict__ W_ih,
                                                    const float* __restrict__ W_hh) {
    const int bm0 = blockIdx.x * 128;
    const int j0  = blockIdx.y * 16;
    const int tid = threadIdx.x;
    const int tx = tid & 15;
    const int ty = tid >> 4;

    __shared__ float As[16][128];
    __shared__ float Bs[16][64];
    __shared__ float stage[64][132];

    float acc[8][4];
    #pragma unroll
    for (int r = 0; r < 8; r++)
        #pragma unroll
        for (int c = 0; c < 4; c++) acc[r][c] = 0.f;

    const int lr = tid >> 2;          // 0..63 (row for A loads; also +64)
    const int kc = (tid & 3) << 2;    // k sub-offset 0,4,8,12
    const int cc = tid >> 2;          // 0..63 local col for B loads
    const int nB = ((cc >> 4) << 10) + j0 + (cc & 15);  // gate*1024 + j

    // ---- phase 1: K over decayed hidden state (1024) ----
    for (int k0 = 0; k0 < HID; k0 += 16) {
        float4 a0 = *(const float4*)&g_hdec[(long)(bm0 + lr) * HID + k0 + kc];
        float4 a1 = *(const float4*)&g_hdec[(long)(bm0 + lr + 64) * HID + k0 + kc];
        float4 b0 = *(const float4*)&W_hh[(long)nB * HID + k0 + kc];
        As[kc+0][lr] = a0.x; As[kc+1][lr] = a0.y; As[kc+2][lr] = a0.z; As[kc+3][lr] = a0.w;
        As[kc+0][lr+64] = a1.x; As[kc+1][lr+64] = a1.y; As[kc+2][lr+64] = a1.z; As[kc+3][lr+64] = a1.w;
        Bs[kc+0][cc] = b0.x; Bs[kc+1][cc] = b0.y; Bs[kc+2][cc] = b0.z; Bs[kc+3][cc] = b0.w;
        __syncthreads();
        #pragma unroll
        for (int k = 0; k < 16; k++) {
            float4 bv  = *(const float4*)&Bs[k][tx << 2];
            float4 av0 = *(const float4*)&As[k][ty << 3];
            float4 av1 = *(const float4*)&As[k][(ty << 3) + 4];
            float a[8] = {av0.x, av0.y, av0.z, av0.w, av1.x, av1.y, av1.z, av1.w};
            float bb[4] = {bv.x, bv.y, bv.z, bv.w};
            #pragma unroll
            for (int r = 0; r < 8; r++)
                #pragma unroll
                for (int c = 0; c < 4; c++)
                    acc[r][c] += a[r] * bb[c];
        }
        __syncthreads();
    }

    // ---- phase 2: K over [x_c, m] inputs (padded to 80, W_ih K=70) ----
    for (int k0 = 0; k0 < INP_PAD; k0 += 16) {
        float4 a0 = *(const float4*)&g_inp[(bm0 + lr) * INP_PAD + k0 + kc];
        float4 a1 = *(const float4*)&g_inp[(bm0 + lr + 64) * INP_PAD + k0 + kc];
        As[kc+0][lr] = a0.x; As[kc+1][lr] = a0.y; As[kc+2][lr] = a0.z; As[kc+3][lr] = a0.w;
        As[kc+0][lr+64] = a1.x; As[kc+1][lr+64] = a1.y; As[kc+2][lr+64] = a1.z; As[kc+3][lr+64] = a1.w;
        #pragma unroll
        for (int i = 0; i < 4; i++) {
            int k = k0 + kc + i;
            Bs[kc + i][cc] = (k < 2 * FEAT) ? W_ih[(long)nB * (2 * FEAT) + k] : 0.f;
        }
        __syncthreads();
        #pragma unroll
        for (int k = 0; k < 16; k++) {
            float4 bv  = *(const float4*)&Bs[k][tx << 2];
            float4 av0 = *(const float4*)&As[k][ty << 3];
            float4 av1 = *(const float4*)&As[k][(ty << 3) + 4];
            float a[8] = {av0.x, av0.y, av0.z, av0.w, av1.x, av1.y, av1.z, av1.w};
            float bb[4] = {bv.x, bv.y, bv.z, bv.w};
            #pragma unroll
            for (int r = 0; r < 8; r++)
                #pragma unroll
                for (int c = 0; c < 4; c++)
                    acc[r][c] += a[r] * bb[c];
        }
        __syncthreads();
    }

    // ---- epilogue: regroup gates, LSTM pointwise ----
    #pragma unroll
    for (int r = 0; r < 8; r++)
        #pragma unroll
        for (int c = 0; c < 4; c++)
            stage[(tx << 2) + c][(ty << 3) + r] = acc[r][c];
    __syncthreads();

    const int bl = tid >> 1;            // 0..127
    const int jb = (tid & 1) << 3;      // 0 or 8
    const int b = bm0 + bl;
    #pragma unroll
    for (int e = 0; e < 8; e++) {
        int jj = jb + e;
        int j = j0 + jj;
        float gi = stage[jj][bl]      + g_bias[j];
        float gf = stage[16 + jj][bl] + g_bias[HID + j];
        float gg = stage[32 + jj][bl] + g_bias[2 * HID + j];
        float go = stage[48 + jj][bl] + g_bias[3 * HID + j];
        float iv = sigmoidf_(gi);
        float fv = sigmoidf_(gf);
        float gv = tanhf(gg);
        float ov = sigmoidf_(go);
        long idx = (long)b * HID + j;
        float cn = fv * g_c[idx] + iv * gv;
        g_c[idx] = cn;
        g_h[idx] = ov * tanhf(cn);
    }
}

// ---------------- final: y_h, predictions, BCE partials ----------------
__global__ void final1_kernel(const float* __restrict__ out_W, const float* __restrict__ out_b,
                              const float* __restrict__ labels, const float* __restrict__ is_train,
                              float* __restrict__ d_out) {
    const int warp = threadIdx.x >> 5, lane = threadIdx.x & 31;
    const int wid = blockIdx.x * 8 + warp;   // 0..255
    float num = 0.f, den = 0.f;
    for (int b = wid; b < BATCH; b += 256) {
        float s = 0.f;
        for (int k = lane; k < HID; k += 32) s += g_h[(long)b * HID + k] * out_W[k];
        s = warp_sum(s);
        if (lane == 0) {
            float yh = s + out_b[0];
            d_out[1 + b] = sigmoidf_(yh);
            float lab = labels[b];
            float it  = is_train[b];
            float mv  = fmaxf(-yh, 0.f);
            float bce = yh - yh * lab + mv + logf(expf(-mv) + expf(-yh - mv));
            num += bce * it;
            den += it;
        }
    }
    if (lane == 0) { atomicAdd(&g_ynum, num); atomicAdd(&g_yden, den); }
}

__global__ void final2_kernel(float* __restrict__ d_out) {
    float xl = 0.f;
    for (int t = 0; t < T_STEPS; t++) xl += g_xnum[t] / (g_mden[t] + 1e-5f);
    float yl = g_ynum / (g_yden + 1e-5f);
    d_out[0] = xl * 0.3f + yl * 1.0f;
}

// ---------------- launch ----------------
extern "C" void kernel_launch(void* const* d_in, const int* in_sizes, int n_in,
                              void* d_out, int out_size) {
    const float* values   = (const float*)d_in[0];
    const float* masks    = (const float*)d_in[1];
    const float* deltas   = (const float*)d_in[2];
    const float* labels   = (const float*)d_in[3];
    const float* is_train = (const float*)d_in[4];
    const float* td_W     = (const float*)d_in[5];
    const float* td_b     = (const float*)d_in[6];
    const float* W_ih     = (const float*)d_in[7];
    const float* W_hh     = (const float*)d_in[8];
    const float* b_ih     = (const float*)d_in[9];
    const float* b_hh     = (const float*)d_in[10];
    const float* reg_W    = (const float*)d_in[11];
    const float* reg_b    = (const float*)d_in[12];
    const float* out_W    = (const float*)d_in[13];
    const float* out_b    = (const float*)d_in[14];
    float* out = (float*)d_out;

    init_kernel<<<4096, 512>>>(b_ih, b_hh);
    gamma_kernel<<<dim3((BATCH * T_STEPS) / 32, HID / 256), 256>>>(deltas, td_W, td_b);
    summask_kernel<<<T_STEPS, 256>>>(masks);

    float* d_imp = out + 1 + BATCH;   // imputations region of output
    for (int t = 0; t < T_STEPS; t++) {
        step1_kernel<<<BATCH / 8, 256>>>(t, values, masks, reg_W, reg_b, d_imp);
        step2_kernel<<<dim3(BATCH / 128, HID / 16), 256>>>(W_ih, W_hh);
    }

    final1_kernel<<<32, 256>>>(out_W, out_b, labels, is_train, out);
    final2_kernel<<<1, 1>>>(out);
}

// round 6
// speedup vs baseline: 1.9005x; 1.9005x over previous
#include <cuda_runtime.h>
#include <cuda_bf16.h>
#include <math.h>
#include <stdint.h>

#define BATCH 4096
#define T_STEPS 48
#define FEAT 35
#define HID 1024
#define GN (4*HID)
#define KTOT 1152          // 1024 (h) + 70 ([x_c,m]) padded to 18*64
#define KCH 64
#define NCHUNK (KTOT/KCH)  // 18
#define TILE_M 128
#define TILE_NJ 64         // j per CTA (x4 gates = 256 N cols)

// smem stage layout (bf16, row pitch 72 elem = 144B, 64 data cols per row)
#define AH_OFF 0
#define AL_OFF 18432
#define BH_OFF 36864
#define BL_OFF 73728
#define STAGE_B 110592
#define SMEM_TOTAL (2*STAGE_B)   // 221184 bytes

// ---------------- device scratch ----------------
__device__ float g_gamma[(size_t)T_STEPS*BATCH*HID];   // [t][b][j]
__device__ __align__(128) __nv_bfloat16 g_Ahi[(size_t)BATCH*KTOT];
__device__ __align__(128) __nv_bfloat16 g_Alo[(size_t)BATCH*KTOT];
__device__ __align__(128) __nv_bfloat16 g_Whi[(size_t)GN*KTOT];
__device__ __align__(128) __nv_bfloat16 g_Wlo[(size_t)GN*KTOT];
__device__ float g_h[(size_t)BATCH*HID];
__device__ float g_c[(size_t)BATCH*HID];
__device__ float g_bias[GN];
__device__ float g_xnum[T_STEPS];
__device__ float g_mden[T_STEPS];
__device__ float g_ynum;
__device__ float g_yden;

// ---------------- helpers ----------------
__device__ __forceinline__ float warp_sum(float v) {
    #pragma unroll
    for (int o = 16; o > 0; o >>= 1) v += __shfl_down_sync(0xffffffffu, v, o);
    return v;
}
__device__ __forceinline__ float sigmoidf_(float x) { return 1.f / (1.f + expf(-x)); }

__device__ __forceinline__ uint32_t s2u(const void* p) {
    uint32_t a;
    asm("{ .reg .u64 t; cvta.to.shared.u64 t, %1; cvt.u32.u64 %0, t; }" : "=r"(a) : "l"(p));
    return a;
}
__device__ __forceinline__ void ldsm4(uint32_t* r, uint32_t addr) {
    asm volatile("ldmatrix.sync.aligned.m8n8.x4.shared.b16 {%0,%1,%2,%3}, [%4];"
        : "=r"(r[0]), "=r"(r[1]), "=r"(r[2]), "=r"(r[3]) : "r"(addr));
}
__device__ __forceinline__ void mma16816(float* d, const uint32_t* a, uint32_t b0, uint32_t b1) {
    asm volatile("mma.sync.aligned.m16n8k16.row.col.f32.bf16.bf16.f32 "
        "{%0,%1,%2,%3}, {%4,%5,%6,%7}, {%8,%9}, {%0,%1,%2,%3};"
        : "+f"(d[0]), "+f"(d[1]), "+f"(d[2]), "+f"(d[3])
        : "r"(a[0]), "r"(a[1]), "r"(a[2]), "r"(a[3]), "r"(b0), "r"(b1));
}
__device__ __forceinline__ void cpasync16(uint32_t saddr, const void* gaddr) {
    asm volatile("cp.async.cg.shared.global [%0], [%1], 16;" :: "r"(saddr), "l"(gaddr));
}

// ---------------- init ----------------
__global__ void init_kernel(const float* __restrict__ b_ih, const float* __restrict__ b_hh) {
    long idx = (long)blockIdx.x * blockDim.x + threadIdx.x;
    long stride = (long)gridDim.x * blockDim.x;
    const long NH = (long)BATCH * HID;
    for (long i = idx; i < NH; i += stride) { g_h[i] = 0.f; g_c[i] = 0.f; }
    uint32_t* ahi = (uint32_t*)g_Ahi;
    uint32_t* alo = (uint32_t*)g_Alo;
    const long NA = (long)BATCH * KTOT / 2;
    for (long i = idx; i < NA; i += stride) { ahi[i] = 0u; alo[i] = 0u; }
    for (long i = idx; i < GN; i += stride) g_bias[i] = b_ih[i] + b_hh[i];
    if (idx < T_STEPS) g_xnum[idx] = 0.f;
    if (idx == 0) { g_ynum = 0.f; g_yden = 0.f; }
}

// ---------------- split weights: Wcat = [W_hh | W_ih | 0] -> bf16 hi/lo ----------------
__global__ void wsplit_kernel(const float* __restrict__ W_ih, const float* __restrict__ W_hh) {
    const int n = blockIdx.x;
    for (int k = threadIdx.x; k < KTOT; k += blockDim.x) {
        float w = 0.f;
        if (k < HID) w = W_hh[(size_t)n * HID + k];
        else if (k < HID + 2 * FEAT) w = W_ih[(size_t)n * (2 * FEAT) + (k - HID)];
        __nv_bfloat16 hi = __float2bfloat16(w);
        g_Whi[(size_t)n * KTOT + k] = hi;
        g_Wlo[(size_t)n * KTOT + k] = __float2bfloat16(w - __bfloat162float(hi));
    }
}

// ---------------- gamma = exp(-relu(deltas @ td_W^T + td_b)), layout [t][b][j] ----------------
__global__ void __launch_bounds__(256) gamma_kernel(const float* __restrict__ deltas,
                                                    const float* __restrict__ td_W,
                                                    const float* __restrict__ td_b) {
    const int r0 = blockIdx.x * 32;
    const int j0 = blockIdx.y * 256;
    __shared__ float sd[32][36];
    __shared__ float sw[256 * FEAT];
    for (int i = threadIdx.x; i < 32 * FEAT; i += 256) {
        int r = i / FEAT, k = i - r * FEAT;
        sd[r][k] = deltas[(long)(r0 + r) * FEAT + k];
    }
    for (int i = threadIdx.x; i < 256 * FEAT; i += 256)
        sw[i] = td_W[(long)j0 * FEAT + i];
    __syncthreads();
    const int c = threadIdx.x;
    float wreg[FEAT];
    #pragma unroll
    for (int k = 0; k < FEAT; k++) wreg[k] = sw[c * FEAT + k];
    const float bias = td_b[j0 + c];
    for (int r = 0; r < 32; r++) {
        float a = bias;
        #pragma unroll
        for (int k = 0; k < FEAT; k++) a += sd[r][k] * wreg[k];
        float rel = fmaxf(a, 0.f);
        int row = r0 + r;
        int b = row / T_STEPS;
        int tt = row - b * T_STEPS;
        g_gamma[((size_t)tt * BATCH + b) * HID + j0 + c] = expf(-rel);
    }
}

// ---------------- per-step sum of masks ----------------
__global__ void summask_kernel(const float* __restrict__ masks) {
    const int t = blockIdx.x;
    float s = 0.f;
    for (int i = threadIdx.x; i < BATCH * FEAT; i += 256) {
        int b = i / FEAT, f = i - b * FEAT;
        s += masks[((long)b * T_STEPS + t) * FEAT + f];
    }
    __shared__ float red[256];
    red[threadIdx.x] = s; __syncthreads();
    for (int o = 128; o > 0; o >>= 1) {
        if (threadIdx.x < o) red[threadIdx.x] += red[threadIdx.x + o];
        __syncthreads();
    }
    if (threadIdx.x == 0) g_mden[t] = red[0];
}

// ---------------- step1: regression GEMV + imputation + x_loss + pack [x_c,m] ----------------
__global__ void __launch_bounds__(256) step1_kernel(int t,
        const float* __restrict__ values, const float* __restrict__ masks,
        const float* __restrict__ reg_W, const float* __restrict__ reg_b,
        float* __restrict__ d_imp) {
    const int tid = threadIdx.x, warp = tid >> 5, lane = tid & 31;
    const int b = blockIdx.x * 8 + warp;
    __shared__ float wl[8];

    // decayed h for this row, reconstructed from bf16 hi/lo planes (written by step2 epi)
    float v[32];
    const __nv_bfloat162* ph = (const __nv_bfloat162*)(g_Ahi + (size_t)b * KTOT);
    const __nv_bfloat162* pl = (const __nv_bfloat162*)(g_Alo + (size_t)b * KTOT);
    #pragma unroll
    for (int i = 0; i < 16; i++) {
        float2 hf = __bfloat1622float2(ph[lane + 32 * i]);
        float2 lf = __bfloat1622float2(pl[lane + 32 * i]);
        v[2 * i]     = hf.x + lf.x;
        v[2 * i + 1] = hf.y + lf.y;
    }

    float lloss = 0.f;
    for (int f = 0; f < FEAT; f++) {
        const float2* pw = (const float2*)(reg_W + (size_t)f * HID);
        float s = 0.f;
        #pragma unroll
        for (int i = 0; i < 16; i++) {
            float2 w = pw[lane + 32 * i];
            s += v[2 * i] * w.x + v[2 * i + 1] * w.y;
        }
        s = warp_sum(s);
        if (lane == 0) {
            float xh = s + reg_b[f];
            size_t off = ((size_t)b * T_STEPS + t) * FEAT + f;
            float x = values[off], m = masks[off];
            float xc = m * x + (1.f - m) * xh;
            d_imp[off] = xc;
            __nv_bfloat16 xhi = __float2bfloat16(xc);
            g_Ahi[(size_t)b * KTOT + HID + f] = xhi;
            g_Alo[(size_t)b * KTOT + HID + f] = __float2bfloat16(xc - __bfloat162float(xhi));
            __nv_bfloat16 mhi = __float2bfloat16(m);
            g_Ahi[(size_t)b * KTOT + HID + FEAT + f] = mhi;
            g_Alo[(size_t)b * KTOT + HID + FEAT + f] = __float2bfloat16(m - __bfloat162float(mhi));
            lloss += fabsf(x - xh) * m;
        }
    }
    if (lane == 0) wl[warp] = lloss;
    __syncthreads();
    if (tid == 0) {
        float s = 0.f;
        #pragma unroll
        for (int w = 0; w < 8; w++) s += wl[w];
        atomicAdd(&g_xnum[t], s);
    }
}

// ---------------- step2: HMMA bf16x3 gates GEMM + fused LSTM epilogue ----------------
// CTA tile 128(M) x 256(N = 4 gates x 64 j). 8 warps, each 64x64.
__global__ void __launch_bounds__(256, 1) step2_hmma(int tnext) {
    extern __shared__ char smem[];
    const int tid = threadIdx.x, lane = tid & 31, wid = tid >> 5;
    const int bm0 = blockIdx.x * TILE_M;
    const int j0  = blockIdx.y * TILE_NJ;
    const uint32_t sbase = s2u(smem);

    const int m0 = (wid & 1) * 64;
    const int n0 = (wid >> 1) * 64;

    float acc[4][8][4];
    #pragma unroll
    for (int mi = 0; mi < 4; mi++)
        #pragma unroll
        for (int nf = 0; nf < 8; nf++)
            #pragma unroll
            for (int r = 0; r < 4; r++) acc[mi][nf][r] = 0.f;

    // ---- prefetch one chunk into stage (c&1) ----
    auto prefetch = [&](int c) {
        const int koff = c * KCH;
        const uint32_t sb = sbase + (c & 1) * STAGE_B;
        #pragma unroll
        for (int i = 0; i < 24; i++) {
            const int id = tid + 256 * i;
            const int row = id >> 3, slot = id & 7;
            const __nv_bfloat16* gp;
            uint32_t soff;
            if (i < 4) {
                gp = g_Ahi + (size_t)(bm0 + row) * KTOT + koff + slot * 8;
                soff = AH_OFF + row * 144 + slot * 16;
            } else if (i < 8) {
                const int r = row - 128;
                gp = g_Alo + (size_t)(bm0 + r) * KTOT + koff + slot * 8;
                soff = AL_OFF + r * 144 + slot * 16;
            } else if (i < 16) {
                const int r = row - 256;
                const int gw = ((r >> 6) << 10) + j0 + (r & 63);
                gp = g_Whi + (size_t)gw * KTOT + koff + slot * 8;
                soff = BH_OFF + r * 144 + slot * 16;
            } else {
                const int r = row - 512;
                const int gw = ((r >> 6) << 10) + j0 + (r & 63);
                gp = g_Wlo + (size_t)gw * KTOT + koff + slot * 8;
                soff = BL_OFF + r * 144 + slot * 16;
            }
            cpasync16(sb + soff, gp);
        }
        asm volatile("cp.async.commit_group;" ::: "memory");
    };

    prefetch(0);
    prefetch(1);

    for (int c = 0; c < NCHUNK; c++) {
        if (c + 1 < NCHUNK) asm volatile("cp.async.wait_group 1;" ::: "memory");
        else                asm volatile("cp.async.wait_group 0;" ::: "memory");
        __syncthreads();
        const uint32_t buf = sbase + (c & 1) * STAGE_B;
        // lane-invariant parts of ldmatrix addresses
        const uint32_t a_l = (uint32_t)((m0 + (lane & 15)) * 144 + (lane >> 4) * 16);
        const uint32_t b_l = (uint32_t)((n0 + ((lane >> 4) << 3) + (lane & 7)) * 144
                                        + ((lane >> 3) & 1) * 16);
        #pragma unroll
        for (int kk = 0; kk < 4; kk++) {
            const uint32_t ko = kk * 32;
            uint32_t ah[4][4], al[4][4], bb[4][4];
            #pragma unroll
            for (int mi = 0; mi < 4; mi++) {
                ldsm4(ah[mi], buf + AH_OFF + a_l + mi * (16 * 144) + ko);
                ldsm4(al[mi], buf + AL_OFF + a_l + mi * (16 * 144) + ko);
            }
            #pragma unroll
            for (int ng = 0; ng < 4; ng++)
                ldsm4(bb[ng], buf + BH_OFF + b_l + ng * (16 * 144) + ko);
            #pragma unroll
            for (int mi = 0; mi < 4; mi++)
                #pragma unroll
                for (int nf = 0; nf < 8; nf++) {
                    mma16816(acc[mi][nf], ah[mi], bb[nf >> 1][(nf & 1) * 2], bb[nf >> 1][(nf & 1) * 2 + 1]);
                }
            #pragma unroll
            for (int mi = 0; mi < 4; mi++)
                #pragma unroll
                for (int nf = 0; nf < 8; nf++) {
                    mma16816(acc[mi][nf], al[mi], bb[nf >> 1][(nf & 1) * 2], bb[nf >> 1][(nf & 1) * 2 + 1]);
                }
            #pragma unroll
            for (int ng = 0; ng < 4; ng++)
                ldsm4(bb[ng], buf + BL_OFF + b_l + ng * (16 * 144) + ko);
            #pragma unroll
            for (int mi = 0; mi < 4; mi++)
                #pragma unroll
                for (int nf = 0; nf < 8; nf++) {
                    mma16816(acc[mi][nf], ah[mi], bb[nf >> 1][(nf & 1) * 2], bb[nf >> 1][(nf & 1) * 2 + 1]);
                }
        }
        __syncthreads();
        if (c + 2 < NCHUNK) prefetch(c + 2);
    }

    // ---- stage gates through smem (float [128][260]) ----
    float* st = (float*)smem;
    #pragma unroll
    for (int mi = 0; mi < 4; mi++) {
        const int mr = m0 + mi * 16 + (lane >> 2);
        #pragma unroll
        for (int nf = 0; nf < 8; nf++) {
            const int nc = n0 + nf * 8 + (lane & 3) * 2;
            st[mr * 260 + nc]           = acc[mi][nf][0];
            st[mr * 260 + nc + 1]       = acc[mi][nf][1];
            st[(mr + 8) * 260 + nc]     = acc[mi][nf][2];
            st[(mr + 8) * 260 + nc + 1] = acc[mi][nf][3];
        }
    }
    __syncthreads();

    // ---- LSTM pointwise + write next decayed bf16 planes ----
    {
        const int jj = tid & 63;
        const int bgrp = tid >> 6;
        const int j = j0 + jj;
        const float bi = g_bias[j];
        const float bf = g_bias[HID + j];
        const float bg = g_bias[2 * HID + j];
        const float bo = g_bias[3 * HID + j];
        for (int e = 0; e < 32; e++) {
            const int bl = bgrp * 32 + e;
            const int b = bm0 + bl;
            float gi = st[bl * 260 + jj]        + bi;
            float gf = st[bl * 260 + 64 + jj]   + bf;
            float gg = st[bl * 260 + 128 + jj]  + bg;
            float go = st[bl * 260 + 192 + jj]  + bo;
            float iv = sigmoidf_(gi);
            float fv = sigmoidf_(gf);
            float gv = tanhf(gg);
            float ov = sigmoidf_(go);
            const size_t idx = (size_t)b * HID + j;
            float cn = fv * g_c[idx] + iv * gv;
            g_c[idx] = cn;
            float h = ov * tanhf(cn);
            g_h[idx] = h;
            float hv = h * g_gamma[((size_t)tnext * BATCH + b) * HID + j];
            __nv_bfloat16 hb = __float2bfloat16(hv);
            g_Ahi[(size_t)b * KTOT + j] = hb;
            g_Alo[(size_t)b * KTOT + j] = __float2bfloat16(hv - __bfloat162float(hb));
        }
    }
}

// ---------------- final: y_h, predictions, BCE partials ----------------
__global__ void final1_kernel(const float* __restrict__ out_W, const float* __restrict__ out_b,
                              const float* __restrict__ labels, const float* __restrict__ is_train,
                              float* __restrict__ d_out) {
    const int warp = threadIdx.x >> 5, lane = threadIdx.x & 31;
    const int wid = blockIdx.x * 8 + warp;
    float num = 0.f, den = 0.f;
    for (int b = wid; b < BATCH; b += 256) {
        float s = 0.f;
        for (int k = lane; k < HID; k += 32) s += g_h[(size_t)b * HID + k] * out_W[k];
        s = warp_sum(s);
        if (lane == 0) {
            float yh = s + out_b[0];
            d_out[1 + b] = sigmoidf_(yh);
            float lab = labels[b];
            float it  = is_train[b];
            float mv  = fmaxf(-yh, 0.f);
            float bce = yh - yh * lab + mv + logf(expf(-mv) + expf(-yh - mv));
            num += bce * it;
            den += it;
        }
    }
    if (lane == 0) { atomicAdd(&g_ynum, num); atomicAdd(&g_yden, den); }
}

__global__ void final2_kernel(float* __restrict__ d_out) {
    float xl = 0.f;
    for (int t = 0; t < T_STEPS; t++) xl += g_xnum[t] / (g_mden[t] + 1e-5f);
    float yl = g_ynum / (g_yden + 1e-5f);
    d_out[0] = xl * 0.3f + yl * 1.0f;
}

// ---------------- launch ----------------
extern "C" void kernel_launch(void* const* d_in, const int* in_sizes, int n_in,
                              void* d_out, int out_size) {
    const float* values   = (const float*)d_in[0];
    const float* masks    = (const float*)d_in[1];
    const float* deltas   = (const float*)d_in[2];
    const float* labels   = (const float*)d_in[3];
    const float* is_train = (const float*)d_in[4];
    const float* td_W     = (const float*)d_in[5];
    const float* td_b     = (const float*)d_in[6];
    const float* W_ih     = (const float*)d_in[7];
    const float* W_hh     = (const float*)d_in[8];
    const float* b_ih     = (const float*)d_in[9];
    const float* b_hh     = (const float*)d_in[10];
    const float* reg_W    = (const float*)d_in[11];
    const float* reg_b    = (const float*)d_in[12];
    const float* out_W    = (const float*)d_in[13];
    const float* out_b    = (const float*)d_in[14];
    float* out = (float*)d_out;

    static int configured = 0;
    if (!configured) {
        cudaFuncSetAttribute(step2_hmma, cudaFuncAttributeMaxDynamicSharedMemorySize, SMEM_TOTAL);
        configured = 1;
    }

    init_kernel<<<4096, 512>>>(b_ih, b_hh);
    wsplit_kernel<<<GN, 128>>>(W_ih, W_hh);
    gamma_kernel<<<dim3((BATCH * T_STEPS) / 32, HID / 256), 256>>>(deltas, td_W, td_b);
    summask_kernel<<<T_STEPS, 256>>>(masks);

    float* d_imp = out + 1 + BATCH;
    for (int t = 0; t < T_STEPS; t++) {
        step1_kernel<<<BATCH / 8, 256>>>(t, values, masks, reg_W, reg_b, d_imp);
        int tnext = (t + 1 < T_STEPS) ? (t + 1) : (T_STEPS - 1);
        step2_hmma<<<dim3(BATCH / TILE_M, HID / TILE_NJ), 256, SMEM_TOTAL>>>(tnext);
    }

    final1_kernel<<<32, 256>>>(out_W, out_b, labels, is_train, out);
    final2_kernel<<<1, 1>>>(out);
}